// round 5
// baseline (speedup 1.0000x reference)
#include <cuda_runtime.h>
#include <cuda_fp16.h>
#include <cstdint>

#define N_NODES 100000
#define N_EDGES 1600000
#define C 128          // IN_C == HID_C == OUT_C == 128

// ---------------- device scratch (no allocations allowed) ----------------
__device__ __half2 g_h[(size_t)N_NODES * C / 2]; // GEMM output, pre-scaled by inv[row], fp16
__device__ float   g_a[(size_t)N_NODES * C];     // layer-1 activation (fp32, GEMM2 input)
__device__ int     g_cnt[N_NODES];               // in-degree counts (excl self-loop)
__device__ int     g_cursor[N_NODES];            // absolute fill cursors (init = rowstart)
__device__ int     g_rowstart[N_NODES + 1];      // CSR row offsets
__device__ float   g_inv[N_NODES];               // 1/sqrt(deg) with self-loop
__device__ int     g_esrc[N_EDGES];              // CSR: src node per slot (grouped by dst)
__device__ int     g_mode64;                     // 1 if edge_index is int64, 0 if int32

// ---------------- probe dtype + zero counts (fused) ----------------
__global__ void probe_zero_kernel(const void* __restrict__ ei) {
    int i = blockIdx.x * blockDim.x + threadIdx.x;
    if (i < N_NODES) g_cnt[i] = 0;
    if (blockIdx.x == 0) {
        __shared__ int bad;
        if (threadIdx.x == 0) bad = 0;
        __syncthreads();
        const long long* p = (const long long*)ei;
        for (int k = threadIdx.x; k < 2048; k += blockDim.x) {
            long long v = p[k];
            if (v < 0 || v >= N_NODES) bad = 1;
        }
        __syncthreads();
        if (threadIdx.x == 0) g_mode64 = bad ? 0 : 1;
    }
}

// ---------------- count: 4 edges per thread ----------------
__global__ void count_kernel(const void* __restrict__ ei) {
    int t = blockIdx.x * blockDim.x + threadIdx.x;        // 0 .. N_EDGES/4-1
    if (t >= N_EDGES / 4) return;
    if (!g_mode64) {
        const int4* dst4 = (const int4*)((const int*)ei + N_EDGES);
        int4 d = dst4[t];
        if ((unsigned)d.x < N_NODES) atomicAdd(&g_cnt[d.x], 1);
        if ((unsigned)d.y < N_NODES) atomicAdd(&g_cnt[d.y], 1);
        if ((unsigned)d.z < N_NODES) atomicAdd(&g_cnt[d.z], 1);
        if ((unsigned)d.w < N_NODES) atomicAdd(&g_cnt[d.w], 1);
    } else {
        const long long* dst = (const long long*)ei + N_EDGES;
        #pragma unroll
        for (int k = 0; k < 4; k++) {
            int d = (int)dst[t * 4 + k];
            if ((unsigned)d < N_NODES) atomicAdd(&g_cnt[d], 1);
        }
    }
}

// ---------------- scan + inv + cursor-init (fused, single block) ----------------
__global__ void scan_inv_kernel() {
    __shared__ int wsum[32];
    const int tid = threadIdx.x;           // 1024 threads
    const int lane = tid & 31, wid = tid >> 5;
    const int CH = (N_NODES + 1023) / 1024;  // 98
    int lo = tid * CH;
    int hi = lo + CH; if (hi > N_NODES) hi = N_NODES;
    if (lo > N_NODES) lo = N_NODES;

    int s = 0;
    for (int i = lo; i < hi; i++) s += g_cnt[i];

    int x = s;
    #pragma unroll
    for (int o = 1; o < 32; o <<= 1) {
        int t = __shfl_up_sync(0xFFFFFFFFu, x, o);
        if (lane >= o) x += t;
    }
    if (lane == 31) wsum[wid] = x;
    __syncthreads();
    if (wid == 0) {
        int w = wsum[lane];
        #pragma unroll
        for (int o = 1; o < 32; o <<= 1) {
            int t = __shfl_up_sync(0xFFFFFFFFu, w, o);
            if (lane >= o) w += t;
        }
        wsum[lane] = w;
    }
    __syncthreads();
    int run = (wid ? wsum[wid - 1] : 0) + x - s;   // exclusive prefix
    for (int i = lo; i < hi; i++) {
        int c = g_cnt[i];
        g_rowstart[i] = run;
        g_cursor[i] = run;
        g_inv[i] = rsqrtf((float)c + 1.0f);
        run += c;
    }
    if (tid == 1023) g_rowstart[N_NODES] = run;
}

// ---------------- fill: 4 edges per thread, absolute cursors ----------------
__global__ void fill_kernel(const void* __restrict__ ei) {
    int t = blockIdx.x * blockDim.x + threadIdx.x;
    if (t >= N_EDGES / 4) return;
    int d[4], s[4];
    if (!g_mode64) {
        const int4* src4 = (const int4*)((const int*)ei);
        const int4* dst4 = (const int4*)((const int*)ei + N_EDGES);
        int4 dv = dst4[t], sv = src4[t];
        d[0] = dv.x; d[1] = dv.y; d[2] = dv.z; d[3] = dv.w;
        s[0] = sv.x; s[1] = sv.y; s[2] = sv.z; s[3] = sv.w;
    } else {
        const long long* srcp = (const long long*)ei;
        const long long* dstp = srcp + N_EDGES;
        #pragma unroll
        for (int k = 0; k < 4; k++) { s[k] = (int)srcp[t * 4 + k]; d[k] = (int)dstp[t * 4 + k]; }
    }
    #pragma unroll
    for (int k = 0; k < 4; k++) {
        if ((unsigned)d[k] < N_NODES && (unsigned)s[k] < N_NODES) {
            int pos = atomicAdd(&g_cursor[d[k]], 1);
            if ((unsigned)pos < N_EDGES) g_esrc[pos] = s[k];
        }
    }
}

// ---------------- tf32 tensor-core GEMM, fp16 pre-scaled output ----------------
__device__ __forceinline__ float cvt_tf32(float x) {
    uint32_t u;
    asm("cvt.rna.tf32.f32 %0, %1;" : "=r"(u) : "f"(x));
    return __uint_as_float(u);
}

__device__ __forceinline__ void mma_tf32(float* c, const uint32_t* a, uint32_t b0, uint32_t b1) {
    asm volatile(
        "mma.sync.aligned.m16n8k8.row.col.f32.tf32.tf32.f32 "
        "{%0,%1,%2,%3},{%4,%5,%6,%7},{%8,%9},{%0,%1,%2,%3};"
        : "+f"(c[0]), "+f"(c[1]), "+f"(c[2]), "+f"(c[3])
        : "r"(a[0]), "r"(a[1]), "r"(a[2]), "r"(a[3]), "r"(b0), "r"(b1));
}

#define GBM 128
template <bool FROM_GA>
__global__ __launch_bounds__(256) void gemm_tf32(const float* __restrict__ Aext,
                                                 const float* __restrict__ W) {
    const float* __restrict__ A = FROM_GA ? g_a : Aext;
    __shared__ float As[GBM][36];   // 128 rows x 32 k (pad -> conflict-free frag loads)
    __shared__ float Bst[C][36];    // transposed W tile: [col][k_local]

    const int tid = threadIdx.x;
    const int lane = tid & 31, wid = tid >> 5;
    const int g = lane >> 2, tig = lane & 3;
    const int rm = (wid & 3) * 32;   // warp row base (4 warps over M)
    const int cn = (wid >> 2) * 64;  // warp col base (2 warps over N)
    const int m0 = blockIdx.x * GBM;

    float acc[2][8][4] = {};

    for (int kk = 0; kk < C; kk += 32) {
        #pragma unroll
        for (int l = 0; l < 4; l++) {
            int slot = tid + l * 256;          // 0..1023
            int row = slot >> 3, kg = slot & 7;
            int gr = m0 + row;
            float4 v = make_float4(0.f, 0.f, 0.f, 0.f);
            if (gr < N_NODES) v = *(const float4*)&A[(size_t)gr * C + kk + kg * 4];
            *(float4*)&As[row][kg * 4] =
                make_float4(cvt_tf32(v.x), cvt_tf32(v.y), cvt_tf32(v.z), cvt_tf32(v.w));
        }
        #pragma unroll
        for (int l = 0; l < 4; l++) {
            int slot = tid + l * 256;
            int kr = slot & 31, cg = slot >> 5;
            float4 w = *(const float4*)&W[(size_t)(kk + kr) * C + cg * 4];
            Bst[cg * 4 + 0][kr] = cvt_tf32(w.x);
            Bst[cg * 4 + 1][kr] = cvt_tf32(w.y);
            Bst[cg * 4 + 2][kr] = cvt_tf32(w.z);
            Bst[cg * 4 + 3][kr] = cvt_tf32(w.w);
        }
        __syncthreads();

        #pragma unroll
        for (int k4 = 0; k4 < 4; k4++) {
            const int k = k4 * 8;
            uint32_t a[2][4];
            #pragma unroll
            for (int i = 0; i < 2; i++) {
                int r = rm + i * 16 + g;
                a[i][0] = __float_as_uint(As[r][k + tig]);
                a[i][1] = __float_as_uint(As[r + 8][k + tig]);
                a[i][2] = __float_as_uint(As[r][k + tig + 4]);
                a[i][3] = __float_as_uint(As[r + 8][k + tig + 4]);
            }
            #pragma unroll
            for (int j = 0; j < 8; j++) {
                int col = cn + j * 8 + g;
                uint32_t b0 = __float_as_uint(Bst[col][k + tig]);
                uint32_t b1 = __float_as_uint(Bst[col][k + tig + 4]);
                mma_tf32(acc[0][j], a[0], b0, b1);
                mma_tf32(acc[1][j], a[1], b0, b1);
            }
        }
        __syncthreads();
    }

    // epilogue: scale row r by g_inv[r], convert to fp16, store half2
    __half* __restrict__ H = (__half*)g_h;
    #pragma unroll
    for (int i = 0; i < 2; i++) {
        int r0 = m0 + rm + i * 16 + g;
        int r1 = r0 + 8;
        float s0 = (r0 < N_NODES) ? g_inv[r0] : 0.f;
        float s1 = (r1 < N_NODES) ? g_inv[r1] : 0.f;
        #pragma unroll
        for (int j = 0; j < 8; j++) {
            int colb = cn + j * 8 + tig * 2;
            if (r0 < N_NODES)
                *(__half2*)&H[(size_t)r0 * C + colb] =
                    __floats2half2_rn(acc[i][j][0] * s0, acc[i][j][1] * s0);
            if (r1 < N_NODES)
                *(__half2*)&H[(size_t)r1 * C + colb] =
                    __floats2half2_rn(acc[i][j][2] * s1, acc[i][j][3] * s1);
        }
    }
}

// ---------------- aggregation: one warp per node, fp16 gather ----------------
// g_h holds hs[r] = inv[r]*h[r] (fp16). out[n] = inv[n]*(sum hs[src] + hs[n]) + bias
template <bool TO_GA>
__global__ __launch_bounds__(256) void agg_kernel(const float* __restrict__ bias,
                                                  float* __restrict__ out) {
    int gw = (blockIdx.x * blockDim.x + threadIdx.x) >> 5;
    int lane = threadIdx.x & 31;
    if (gw >= N_NODES) return;
    const int n = gw;
    const uint2* __restrict__ hv = (const uint2*)g_h;   // 32 uint2 per row

    float4 acc = make_float4(0.f, 0.f, 0.f, 0.f);
    const int e0 = g_rowstart[n];
    const int e1 = g_rowstart[n + 1];
    int e = e0;
    for (; e + 4 <= e1; e += 4) {
        int s0 = g_esrc[e + 0], s1 = g_esrc[e + 1], s2 = g_esrc[e + 2], s3 = g_esrc[e + 3];
        uint2 u0 = hv[(size_t)s0 * 32 + lane];
        uint2 u1 = hv[(size_t)s1 * 32 + lane];
        uint2 u2 = hv[(size_t)s2 * 32 + lane];
        uint2 u3 = hv[(size_t)s3 * 32 + lane];
        float2 a0 = __half22float2(*(__half2*)&u0.x), b0 = __half22float2(*(__half2*)&u0.y);
        float2 a1 = __half22float2(*(__half2*)&u1.x), b1 = __half22float2(*(__half2*)&u1.y);
        float2 a2 = __half22float2(*(__half2*)&u2.x), b2 = __half22float2(*(__half2*)&u2.y);
        float2 a3 = __half22float2(*(__half2*)&u3.x), b3 = __half22float2(*(__half2*)&u3.y);
        acc.x += (a0.x + a1.x) + (a2.x + a3.x);
        acc.y += (a0.y + a1.y) + (a2.y + a3.y);
        acc.z += (b0.x + b1.x) + (b2.x + b3.x);
        acc.w += (b0.y + b1.y) + (b2.y + b3.y);
    }
    for (; e < e1; e++) {
        int s = g_esrc[e];
        uint2 u = hv[(size_t)s * 32 + lane];
        float2 a = __half22float2(*(__half2*)&u.x), b = __half22float2(*(__half2*)&u.y);
        acc.x += a.x; acc.y += a.y; acc.z += b.x; acc.w += b.y;
    }

    const float invd = g_inv[n];
    uint2 us = hv[(size_t)n * 32 + lane];
    float2 ha = __half22float2(*(__half2*)&us.x), hb = __half22float2(*(__half2*)&us.y);
    float4 bb = ((const float4*)bias)[lane];
    float4 o;
    o.x = invd * (acc.x + ha.x) + bb.x;
    o.y = invd * (acc.y + ha.y) + bb.y;
    o.z = invd * (acc.z + hb.x) + bb.z;
    o.w = invd * (acc.w + hb.y) + bb.w;
    if (TO_GA) {
        o.x = fmaxf(o.x, 0.f); o.y = fmaxf(o.y, 0.f);
        o.z = fmaxf(o.z, 0.f); o.w = fmaxf(o.w, 0.f);
        ((float4*)g_a)[(size_t)n * 32 + lane] = o;
    } else {
        ((float4*)out)[(size_t)n * 32 + lane] = o;
    }
}

// ---------------- launch (kernel launches ONLY) ----------------
extern "C" void kernel_launch(void* const* d_in, const int* in_sizes, int n_in,
                              void* d_out, int out_size) {
    const float* x  = (const float*)d_in[0];
    const void*  ei = d_in[1];
    const float* W1 = (const float*)d_in[2];
    const float* b1 = (const float*)d_in[3];
    const float* W2 = (const float*)d_in[4];
    const float* b2 = (const float*)d_in[5];
    float* out = (float*)d_out;

    const int TB = 256;
    const int nodeBlocks = (N_NODES + TB - 1) / TB;
    const int edge4Blocks = (N_EDGES / 4 + TB - 1) / TB;
    const int gemmBlocks = (N_NODES + GBM - 1) / GBM;
    const int aggBlocks = (N_NODES * 32 + TB - 1) / TB;

    // CSR build (shared by both layers)
    probe_zero_kernel<<<nodeBlocks, TB>>>(ei);
    count_kernel<<<edge4Blocks, TB>>>(ei);
    scan_inv_kernel<<<1, 1024>>>();
    fill_kernel<<<edge4Blocks, TB>>>(ei);

    // layer 1: g_h = fp16(inv .* (x@W1)) ; g_a = relu(agg + b1)
    gemm_tf32<false><<<gemmBlocks, TB>>>(x, W1);
    agg_kernel<true><<<aggBlocks, TB>>>(b1, nullptr);

    // layer 2: g_h = fp16(inv .* (g_a@W2)) ; out = agg + b2
    gemm_tf32<true><<<gemmBlocks, TB>>>(nullptr, W2);
    agg_kernel<false><<<aggBlocks, TB>>>(b2, out);
}

// round 6
// speedup vs baseline: 1.0069x; 1.0069x over previous
#include <cuda_runtime.h>
#include <cuda_fp16.h>
#include <cstdint>

#define N_NODES 100000
#define N_EDGES 1600000
#define C 128          // IN_C == HID_C == OUT_C == 128

// ---------------- device scratch (no allocations allowed) ----------------
__device__ __half2 g_h[(size_t)N_NODES * C / 2]; // GEMM output, pre-scaled by inv[row], fp16
__device__ float   g_a[(size_t)N_NODES * C];     // layer-1 activation (fp32, GEMM2 input)
__device__ int     g_cnt[N_NODES];               // in-degree counts (excl self-loop)
__device__ int     g_cursor[N_NODES];            // absolute fill cursors (init = rowstart)
__device__ int     g_rowstart[N_NODES + 1];      // CSR row offsets
__device__ float   g_inv[N_NODES];               // 1/sqrt(deg) with self-loop
__device__ int     g_esrc[N_EDGES];              // CSR: src node per slot (grouped by dst)
__device__ int     g_mode64;                     // 1 if edge_index is int64, 0 if int32

// ---------------- probe dtype + zero counts (fused) ----------------
__global__ void probe_zero_kernel(const void* __restrict__ ei) {
    int i = blockIdx.x * blockDim.x + threadIdx.x;
    if (i < N_NODES) g_cnt[i] = 0;
    if (blockIdx.x == 0) {
        __shared__ int bad;
        if (threadIdx.x == 0) bad = 0;
        __syncthreads();
        const long long* p = (const long long*)ei;
        for (int k = threadIdx.x; k < 2048; k += blockDim.x) {
            long long v = p[k];
            if (v < 0 || v >= N_NODES) bad = 1;
        }
        __syncthreads();
        if (threadIdx.x == 0) g_mode64 = bad ? 0 : 1;
    }
}

// ---------------- count: 4 edges per thread ----------------
__global__ void count_kernel(const void* __restrict__ ei) {
    int t = blockIdx.x * blockDim.x + threadIdx.x;        // 0 .. N_EDGES/4-1
    if (t >= N_EDGES / 4) return;
    if (!g_mode64) {
        const int4* dst4 = (const int4*)((const int*)ei + N_EDGES);
        int4 d = dst4[t];
        if ((unsigned)d.x < N_NODES) atomicAdd(&g_cnt[d.x], 1);
        if ((unsigned)d.y < N_NODES) atomicAdd(&g_cnt[d.y], 1);
        if ((unsigned)d.z < N_NODES) atomicAdd(&g_cnt[d.z], 1);
        if ((unsigned)d.w < N_NODES) atomicAdd(&g_cnt[d.w], 1);
    } else {
        const long long* dst = (const long long*)ei + N_EDGES;
        #pragma unroll
        for (int k = 0; k < 4; k++) {
            int d = (int)dst[t * 4 + k];
            if ((unsigned)d < N_NODES) atomicAdd(&g_cnt[d], 1);
        }
    }
}

// ---------------- scan + inv + cursor-init (fused, single block) ----------------
__global__ void scan_inv_kernel() {
    __shared__ int wsum[32];
    const int tid = threadIdx.x;           // 1024 threads
    const int lane = tid & 31, wid = tid >> 5;
    const int CH = (N_NODES + 1023) / 1024;  // 98
    int lo = tid * CH;
    int hi = lo + CH; if (hi > N_NODES) hi = N_NODES;
    if (lo > N_NODES) lo = N_NODES;

    int s = 0;
    for (int i = lo; i < hi; i++) s += g_cnt[i];

    int x = s;
    #pragma unroll
    for (int o = 1; o < 32; o <<= 1) {
        int t = __shfl_up_sync(0xFFFFFFFFu, x, o);
        if (lane >= o) x += t;
    }
    if (lane == 31) wsum[wid] = x;
    __syncthreads();
    if (wid == 0) {
        int w = wsum[lane];
        #pragma unroll
        for (int o = 1; o < 32; o <<= 1) {
            int t = __shfl_up_sync(0xFFFFFFFFu, w, o);
            if (lane >= o) w += t;
        }
        wsum[lane] = w;
    }
    __syncthreads();
    int run = (wid ? wsum[wid - 1] : 0) + x - s;   // exclusive prefix
    for (int i = lo; i < hi; i++) {
        int c = g_cnt[i];
        g_rowstart[i] = run;
        g_cursor[i] = run;
        g_inv[i] = rsqrtf((float)c + 1.0f);
        run += c;
    }
    if (tid == 1023) g_rowstart[N_NODES] = run;
}

// ---------------- fill: 4 edges per thread, absolute cursors ----------------
__global__ void fill_kernel(const void* __restrict__ ei) {
    int t = blockIdx.x * blockDim.x + threadIdx.x;
    if (t >= N_EDGES / 4) return;
    int d[4], s[4];
    if (!g_mode64) {
        const int4* src4 = (const int4*)((const int*)ei);
        const int4* dst4 = (const int4*)((const int*)ei + N_EDGES);
        int4 dv = dst4[t], sv = src4[t];
        d[0] = dv.x; d[1] = dv.y; d[2] = dv.z; d[3] = dv.w;
        s[0] = sv.x; s[1] = sv.y; s[2] = sv.z; s[3] = sv.w;
    } else {
        const long long* srcp = (const long long*)ei;
        const long long* dstp = srcp + N_EDGES;
        #pragma unroll
        for (int k = 0; k < 4; k++) { s[k] = (int)srcp[t * 4 + k]; d[k] = (int)dstp[t * 4 + k]; }
    }
    #pragma unroll
    for (int k = 0; k < 4; k++) {
        if ((unsigned)d[k] < N_NODES && (unsigned)s[k] < N_NODES) {
            int pos = atomicAdd(&g_cursor[d[k]], 1);
            if ((unsigned)pos < N_EDGES) g_esrc[pos] = s[k];
        }
    }
}

// ---------------- tf32 tensor-core GEMM, fp16 pre-scaled output ----------------
__device__ __forceinline__ float cvt_tf32(float x) {
    uint32_t u;
    asm("cvt.rna.tf32.f32 %0, %1;" : "=r"(u) : "f"(x));
    return __uint_as_float(u);
}

__device__ __forceinline__ void mma_tf32(float* c, const uint32_t* a, uint32_t b0, uint32_t b1) {
    asm volatile(
        "mma.sync.aligned.m16n8k8.row.col.f32.tf32.tf32.f32 "
        "{%0,%1,%2,%3},{%4,%5,%6,%7},{%8,%9},{%0,%1,%2,%3};"
        : "+f"(c[0]), "+f"(c[1]), "+f"(c[2]), "+f"(c[3])
        : "r"(a[0]), "r"(a[1]), "r"(a[2]), "r"(a[3]), "r"(b0), "r"(b1));
}

#define GBM 128
template <bool FROM_GA>
__global__ __launch_bounds__(256) void gemm_tf32(const float* __restrict__ Aext,
                                                 const float* __restrict__ W) {
    const float* __restrict__ A = FROM_GA ? g_a : Aext;
    __shared__ float As[GBM][36];   // 128 rows x 32 k (pad -> conflict-free frag loads)
    __shared__ float Bst[C][36];    // transposed W tile: [col][k_local]

    const int tid = threadIdx.x;
    const int lane = tid & 31, wid = tid >> 5;
    const int g = lane >> 2, tig = lane & 3;
    const int rm = (wid & 3) * 32;   // warp row base (4 warps over M)
    const int cn = (wid >> 2) * 64;  // warp col base (2 warps over N)
    const int m0 = blockIdx.x * GBM;

    float acc[2][8][4] = {};

    for (int kk = 0; kk < C; kk += 32) {
        #pragma unroll
        for (int l = 0; l < 4; l++) {
            int slot = tid + l * 256;          // 0..1023
            int row = slot >> 3, kg = slot & 7;
            int gr = m0 + row;
            float4 v = make_float4(0.f, 0.f, 0.f, 0.f);
            if (gr < N_NODES) v = *(const float4*)&A[(size_t)gr * C + kk + kg * 4];
            *(float4*)&As[row][kg * 4] =
                make_float4(cvt_tf32(v.x), cvt_tf32(v.y), cvt_tf32(v.z), cvt_tf32(v.w));
        }
        #pragma unroll
        for (int l = 0; l < 4; l++) {
            int slot = tid + l * 256;
            int kr = slot & 31, cg = slot >> 5;
            float4 w = *(const float4*)&W[(size_t)(kk + kr) * C + cg * 4];
            Bst[cg * 4 + 0][kr] = cvt_tf32(w.x);
            Bst[cg * 4 + 1][kr] = cvt_tf32(w.y);
            Bst[cg * 4 + 2][kr] = cvt_tf32(w.z);
            Bst[cg * 4 + 3][kr] = cvt_tf32(w.w);
        }
        __syncthreads();

        #pragma unroll
        for (int k4 = 0; k4 < 4; k4++) {
            const int k = k4 * 8;
            uint32_t a[2][4];
            #pragma unroll
            for (int i = 0; i < 2; i++) {
                int r = rm + i * 16 + g;
                a[i][0] = __float_as_uint(As[r][k + tig]);
                a[i][1] = __float_as_uint(As[r + 8][k + tig]);
                a[i][2] = __float_as_uint(As[r][k + tig + 4]);
                a[i][3] = __float_as_uint(As[r + 8][k + tig + 4]);
            }
            #pragma unroll
            for (int j = 0; j < 8; j++) {
                int col = cn + j * 8 + g;
                uint32_t b0 = __float_as_uint(Bst[col][k + tig]);
                uint32_t b1 = __float_as_uint(Bst[col][k + tig + 4]);
                mma_tf32(acc[0][j], a[0], b0, b1);
                mma_tf32(acc[1][j], a[1], b0, b1);
            }
        }
        __syncthreads();
    }

    // epilogue: scale row r by g_inv[r], convert to fp16, store half2 (register-only pack)
    __half* __restrict__ H = (__half*)g_h;
    #pragma unroll
    for (int i = 0; i < 2; i++) {
        int r0 = m0 + rm + i * 16 + g;
        int r1 = r0 + 8;
        float s0 = (r0 < N_NODES) ? g_inv[r0] : 0.f;
        float s1 = (r1 < N_NODES) ? g_inv[r1] : 0.f;
        #pragma unroll
        for (int j = 0; j < 8; j++) {
            int colb = cn + j * 8 + tig * 2;
            if (r0 < N_NODES) {
                uint32_t p;
                asm("cvt.rn.f16x2.f32 %0, %1, %2;" : "=r"(p)
                    : "f"(acc[i][j][1] * s0), "f"(acc[i][j][0] * s0));
                *(uint32_t*)&H[(size_t)r0 * C + colb] = p;
            }
            if (r1 < N_NODES) {
                uint32_t p;
                asm("cvt.rn.f16x2.f32 %0, %1, %2;" : "=r"(p)
                    : "f"(acc[i][j][3] * s1), "f"(acc[i][j][2] * s1));
                *(uint32_t*)&H[(size_t)r1 * C + colb] = p;
            }
        }
    }
}

// ---------------- aggregation: one warp per node, fp16 gather (register-only cvt) ----
// g_h holds hs[r] = inv[r]*h[r] (fp16). out[n] = inv[n]*(sum hs[src] + hs[n]) + bias
__device__ __forceinline__ void acc_h2x2(uint2 u, float4& acc) {
    asm("{\n\t"
        ".reg .f16 l0, h0, l1, h1;\n\t"
        ".reg .f32 f0, f1, f2, f3;\n\t"
        "mov.b32 {l0, h0}, %4;\n\t"
        "mov.b32 {l1, h1}, %5;\n\t"
        "cvt.f32.f16 f0, l0;\n\t"
        "cvt.f32.f16 f1, h0;\n\t"
        "cvt.f32.f16 f2, l1;\n\t"
        "cvt.f32.f16 f3, h1;\n\t"
        "add.f32 %0, %0, f0;\n\t"
        "add.f32 %1, %1, f1;\n\t"
        "add.f32 %2, %2, f2;\n\t"
        "add.f32 %3, %3, f3;\n\t"
        "}"
        : "+f"(acc.x), "+f"(acc.y), "+f"(acc.z), "+f"(acc.w)
        : "r"(u.x), "r"(u.y));
}

template <bool TO_GA>
__global__ __launch_bounds__(256) void agg_kernel(const float* __restrict__ bias,
                                                  float* __restrict__ out) {
    int gw = (blockIdx.x * blockDim.x + threadIdx.x) >> 5;
    int lane = threadIdx.x & 31;
    if (gw >= N_NODES) return;
    const int n = gw;
    const uint2* __restrict__ hv = (const uint2*)g_h;   // 32 uint2 per 256B row

    float4 acc = make_float4(0.f, 0.f, 0.f, 0.f);
    const int e0 = g_rowstart[n];
    const int e1 = g_rowstart[n + 1];
    int e = e0;
    // 8 outstanding gathers per iteration for MLP
    for (; e + 8 <= e1; e += 8) {
        uint2 u[8];
        #pragma unroll
        for (int k = 0; k < 8; k++) {
            int s = g_esrc[e + k];
            u[k] = hv[(size_t)s * 32 + lane];
        }
        #pragma unroll
        for (int k = 0; k < 8; k++) acc_h2x2(u[k], acc);
    }
    if (e + 4 <= e1) {
        uint2 u[4];
        #pragma unroll
        for (int k = 0; k < 4; k++) {
            int s = g_esrc[e + k];
            u[k] = hv[(size_t)s * 32 + lane];
        }
        #pragma unroll
        for (int k = 0; k < 4; k++) acc_h2x2(u[k], acc);
        e += 4;
    }
    for (; e < e1; e++) {
        int s = g_esrc[e];
        acc_h2x2(hv[(size_t)s * 32 + lane], acc);
    }

    const float invd = g_inv[n];
    float4 self = make_float4(0.f, 0.f, 0.f, 0.f);
    acc_h2x2(hv[(size_t)n * 32 + lane], self);
    float4 bb = ((const float4*)bias)[lane];
    float4 o;
    o.x = invd * (acc.x + self.x) + bb.x;
    o.y = invd * (acc.y + self.y) + bb.y;
    o.z = invd * (acc.z + self.z) + bb.z;
    o.w = invd * (acc.w + self.w) + bb.w;
    if (TO_GA) {
        o.x = fmaxf(o.x, 0.f); o.y = fmaxf(o.y, 0.f);
        o.z = fmaxf(o.z, 0.f); o.w = fmaxf(o.w, 0.f);
        ((float4*)g_a)[(size_t)n * 32 + lane] = o;
    } else {
        ((float4*)out)[(size_t)n * 32 + lane] = o;
    }
}

// ---------------- launch (kernel launches ONLY) ----------------
extern "C" void kernel_launch(void* const* d_in, const int* in_sizes, int n_in,
                              void* d_out, int out_size) {
    const float* x  = (const float*)d_in[0];
    const void*  ei = d_in[1];
    const float* W1 = (const float*)d_in[2];
    const float* b1 = (const float*)d_in[3];
    const float* W2 = (const float*)d_in[4];
    const float* b2 = (const float*)d_in[5];
    float* out = (float*)d_out;

    const int TB = 256;
    const int nodeBlocks = (N_NODES + TB - 1) / TB;
    const int edge4Blocks = (N_EDGES / 4 + TB - 1) / TB;
    const int gemmBlocks = (N_NODES + GBM - 1) / GBM;
    const int aggBlocks = (N_NODES * 32 + TB - 1) / TB;

    // CSR build (shared by both layers)
    probe_zero_kernel<<<nodeBlocks, TB>>>(ei);
    count_kernel<<<edge4Blocks, TB>>>(ei);
    scan_inv_kernel<<<1, 1024>>>();
    fill_kernel<<<edge4Blocks, TB>>>(ei);

    // layer 1: g_h = fp16(inv .* (x@W1)) ; g_a = relu(agg + b1)
    gemm_tf32<false><<<gemmBlocks, TB>>>(x, W1);
    agg_kernel<true><<<aggBlocks, TB>>>(b1, nullptr);

    // layer 2: g_h = fp16(inv .* (g_a@W2)) ; out = agg + b2
    gemm_tf32<true><<<gemmBlocks, TB>>>(nullptr, W2);
    agg_kernel<false><<<aggBlocks, TB>>>(b2, out);
}